// round 6
// baseline (speedup 1.0000x reference)
#include <cuda_runtime.h>
#include <cuda_bf16.h>

#define BN 32

// ---- packed target bitmask pyramids ----
#define NW0 (BN * 512 * 16)   // 262144 words, L0: [32][512][16]
#define NW1 (BN * 256 * 8)    //  65536 words, L1: [32][256][8]
#define NW2 (BN * 128 * 4)    //  16384 words, L2: [32][128][4]
#define NWT (NW0 + NW1 + NW2) // 344064
__device__ unsigned g_bits[NWT];

// ---- per-block partials ----
#define BPI0 32
#define BPI1 8
#define BPI2 2
#define NB0 (BN * BPI0)        // 1024
#define NB1 (BN * BPI1)        // 256
#define NB2 (BN * BPI2)        // 64
#define NBLK (NB2 + NB1 + NB0) // 1344
__device__ float g_part[NBLK * 5];
__device__ unsigned g_count = 0;

__device__ __forceinline__ float warp_sum(float v) {
    #pragma unroll
    for (int o = 16; o > 0; o >>= 1) v += __shfl_down_sync(0xffffffffu, v, o);
    return v;
}

__device__ __forceinline__ float fsigmoid(float x) {
    return __fdividef(1.0f, 1.0f + __expf(-x));
}

// ================= pack pass: targets -> 1 bit/pixel, 3 pyramids =================
__global__ void __launch_bounds__(256)
pack_kernel(const int* __restrict__ tg) {
    const int lane  = threadIdx.x & 31;
    const int gwarp = (blockIdx.x * blockDim.x + threadIdx.x) >> 5;
    const int nwarp = (gridDim.x * blockDim.x) >> 5;
    // groups of 4 consecutive words (same level, 4 independent loads for MLP)
    for (int g = gwarp; g < NWT / 4; g += nwarp) {
        const int w0 = g << 2;
        unsigned res[4];
        #pragma unroll
        for (int k = 0; k < 4; k++) {
            const int w = w0 + k;
            int img, row, colb, st;
            if (w < NW0)              { int r = w;              img = r >> 13; r &= 8191; row = r >> 4; colb = (r & 15) << 5; st = 1; }
            else if (w < NW0 + NW1)   { int r = w - NW0;        img = r >> 11; r &= 2047; row = r >> 3; colb = (r & 7)  << 5; st = 2; }
            else                      { int r = w - NW0 - NW1;  img = r >> 9;  r &= 511;  row = r >> 2; colb = (r & 3)  << 5; st = 4; }
            const int v = tg[((size_t)img << 18) + (size_t)(row * st) * 512 + (colb + lane) * st];
            res[k] = __ballot_sync(0xffffffffu, v != 0);
        }
        if (lane < 4) g_bits[w0 + lane] = res[lane];  // lanes 0-3 each hold their own ballot? no:
    }
}

// NOTE on the write above: every lane holds all res[k] (ballot is warp-uniform),
// so lane<4 writing res[lane] is correct and coalesced.

// ================= main fused kernel =================
struct Acc { float c, s, inter, z, ps; };

__device__ __forceinline__ void commit(Acc& a, int slot, float* s_red) {
    a.c     = warp_sum(a.c);
    a.s     = warp_sum(a.s);
    a.inter = warp_sum(a.inter);
    a.z     = warp_sum(a.z);
    a.ps    = warp_sum(a.ps);
    const int wid = threadIdx.x >> 5;
    if ((threadIdx.x & 31) == 0) {
        float* r = s_red + wid * 5;
        r[0] = a.c; r[1] = a.s; r[2] = a.inter; r[3] = a.z; r[4] = a.ps;
    }
    __syncthreads();
    if (threadIdx.x == 0) {
        float o0 = 0.f, o1 = 0.f, o2 = 0.f, o3 = 0.f, o4 = 0.f;
        #pragma unroll
        for (int w = 0; w < 8; w++) {
            o0 += s_red[w * 5 + 0]; o1 += s_red[w * 5 + 1]; o2 += s_red[w * 5 + 2];
            o3 += s_red[w * 5 + 3]; o4 += s_red[w * 5 + 4];
        }
        float* g = &g_part[slot * 5];
        g[0] = o0; g[1] = o1; g[2] = o2; g[3] = o3; g[4] = o4;
    }
}

// One 32-pixel word-task per thread. H rows, WPR words/row (LOG2W = log2(WPR)).
template<int H, int WPR, int LOG2W>
__device__ Acc do_scale(const float* __restrict__ logits,
                        const unsigned* __restrict__ bits,
                        int img, int blk) {
    const int t   = blk * 256 + threadIdx.x;     // [0, H*WPR)
    const int row = t >> LOG2W;
    const int wc  = t & (WPR - 1);

    const unsigned* bw = bits + img * (H * WPR) + t;
    const unsigned ctr = bw[0];
    const unsigned up  = (row > 0)       ? bw[-WPR] : 0u;
    const unsigned dn  = (row < H - 1)   ? bw[ WPR] : 0u;
    const unsigned pv  = (wc > 0)        ? bw[-1]   : 0u;
    const unsigned nx  = (wc < WPR - 1)  ? bw[ 1]   : 0u;
    const unsigned Lm  = (ctr << 1) | (pv >> 31);
    const unsigned Rm  = (ctr >> 1) | (nx << 31);
    const unsigned bnd = ctr & ~(up & dn & Lm & Rm);

    Acc a;
    a.s  = (float)__popc(ctr);
    a.c  = (float)__popc(bnd);
    a.ps = 0.f; a.z = 0.f; a.inter = 0.f;

    const float* lp = logits + (size_t)img * (H * WPR * 32) + ((size_t)t << 5);
    #pragma unroll
    for (int q = 0; q < 8; q++) {
        const float4 x = reinterpret_cast<const float4*>(lp)[q];
        const float p0 = fsigmoid(x.x), p1 = fsigmoid(x.y),
                    p2 = fsigmoid(x.z), p3 = fsigmoid(x.w);
        a.ps += (p0 + p1) + (p2 + p3);
        a.z  += (p0 * p0 + p1 * p1) + (p2 * p2 + p3 * p3);
        const unsigned bq = ctr >> (q * 4);
        a.inter += (bq & 1u) ? p0 : 0.f;
        a.inter += (bq & 2u) ? p1 : 0.f;
        a.inter += (bq & 4u) ? p2 : 0.f;
        a.inter += (bq & 8u) ? p3 : 0.f;
    }
    return a;
}

__global__ void __launch_bounds__(256)
fused_kernel(const float* __restrict__ l0,
             const float* __restrict__ l1,
             const float* __restrict__ l2,
             const float* __restrict__ vm,
             float* __restrict__ out) {
    __shared__ float s_red[8 * 5];
    __shared__ bool  s_last;
    __shared__ float s_contrib[96];
    __shared__ float s_valid[BN];

    const int bid = blockIdx.x;
    Acc a;
    if (bid < NB2) {                                   // scale 2: 128x128, 512 tasks/img
        a = do_scale<128, 4, 2>(l2, g_bits + NW0 + NW1, bid / BPI2, bid % BPI2);
    } else if (bid < NB2 + NB1) {                      // scale 1: 256x256, 2048 tasks/img
        const int b = bid - NB2;
        a = do_scale<256, 8, 3>(l1, g_bits + NW0, b / BPI1, b % BPI1);
    } else {                                           // scale 0: 512x512, 8192 tasks/img
        const int b = bid - NB2 - NB1;
        a = do_scale<512, 16, 4>(l0, g_bits, b / BPI0, b % BPI0);
    }
    commit(a, bid, s_red);

    __syncthreads();
    if (threadIdx.x == 0) {
        __threadfence();
        unsigned r = atomicAdd(&g_count, 1u);
        s_last = (r == NBLK - 1);
    }
    __syncthreads();
    if (!s_last) return;

    const int tid = threadIdx.x;
    if (tid == 0) g_count = 0;
    if (tid < BN) s_valid[tid] = (vm[tid] >= 0.5f) ? 1.0f : 0.0f;
    __syncthreads();

    if (tid < 96) {
        const int sc  = tid >> 5;   // 0=scale0, 1=scale1, 2=scale2
        const int img = tid & 31;
        int base, cntb;
        if      (sc == 0) { base = (NB2 + NB1) + img * BPI0; cntb = BPI0; }
        else if (sc == 1) { base = NB2 + img * BPI1;         cntb = BPI1; }
        else              { base = img * BPI2;               cntb = BPI2; }

        float C = 0.f, S = 0.f, I = 0.f, Z = 0.f, P = 0.f;
        for (int b = 0; b < cntb; b++) {
            const float* g = &g_part[(base + b) * 5];
            C += g[0]; S += g[1]; I += g[2]; Z += g[3]; P += g[4];
        }
        const float SMOOTH = 1e-5f;
        const float ws[3]     = { 1.0f / 1.75f, 0.5f / 1.75f, 0.25f / 1.75f };
        const float inv_hw[3] = { 1.0f / (512.f * 512.f), 1.0f / (256.f * 256.f), 1.0f / (128.f * 128.f) };
        float alpha = 2.0f * (1.0f - (C + SMOOTH) / (S + SMOOTH)) - 1.0f;
        alpha = fminf(alpha, 0.8f);
        const float num = Z + S - 2.0f * I + SMOOTH;
        const float den = Z + S - (1.0f + alpha) * I + SMOOTH;
        const float dou = num / den;
        const float per = (S > 0.f) ? dou : P * inv_hw[sc];
        s_contrib[tid] = ws[sc] * per * s_valid[img];
    }
    __syncthreads();
    if (tid == 0) {
        float sum = 0.f, cnt = 0.f;
        #pragma unroll
        for (int i = 0; i < 96; i++) sum += s_contrib[i];
        #pragma unroll
        for (int i = 0; i < BN; i++) cnt += s_valid[i];
        out[0] = (cnt > 0.f) ? (sum / cnt) : 0.0f;
    }
}

extern "C" void kernel_launch(void* const* d_in, const int* in_sizes, int n_in,
                              void* d_out, int out_size) {
    const float* l0 = (const float*)d_in[0];   // [8,4,512,512]
    const float* l1 = (const float*)d_in[1];   // [8,4,256,256]
    const float* l2 = (const float*)d_in[2];   // [8,4,128,128]
    const int*   tg = (const int*)d_in[3];     // [8,4,512,512]
    const float* vm = (const float*)d_in[4];   // [8,4]
    float* out = (float*)d_out;

    pack_kernel<<<1024, 256>>>(tg);
    fused_kernel<<<NBLK, 256>>>(l0, l1, l2, vm, out);
}

// round 7
// speedup vs baseline: 1.3028x; 1.3028x over previous
#include <cuda_runtime.h>
#include <cuda_bf16.h>

#define BN 32

// ---- packed target bitmask pyramids ----
#define NW0 (BN * 512 * 16)   // 262144 words, L0: [32][512][16]
#define NW1 (BN * 256 * 8)    //  65536 words, L1: [32][256][8]
#define NW2 (BN * 128 * 4)    //  16384 words, L2: [32][128][4]
__device__ unsigned g_bits[NW0 + NW1 + NW2];

// ---- per-block partials ----
#define BPI0 32
#define BPI1 8
#define BPI2 2
#define NB0 (BN * BPI0)        // 1024
#define NB1 (BN * BPI1)        // 256
#define NB2 (BN * BPI2)        // 64
#define NBLK (NB2 + NB1 + NB0) // 1344
__device__ float g_part[NBLK * 5];
__device__ unsigned g_count = 0;

__device__ __forceinline__ float warp_sum(float v) {
    #pragma unroll
    for (int o = 16; o > 0; o >>= 1) v += __shfl_down_sync(0xffffffffu, v, o);
    return v;
}

__device__ __forceinline__ float fsigmoid(float x) {
    return __fdividef(1.0f, 1.0f + __expf(-x));
}

// ============ pack: one coalesced pass over targets, all 3 levels ============
// Per warp-iteration: 128 consecutive pixels of one row (int4 per lane, 2KB coalesced).
// L0 words via 8-lane butterfly-OR; L1 (even rows) via 16-lane; L2 (rows%4==0) via 32-lane.
__global__ void __launch_bounds__(256)
pack_kernel(const int* __restrict__ tg) {
    const int lane = threadIdx.x & 31;
    const int wg   = (blockIdx.x * 256 + threadIdx.x) >> 5;   // global warp id
    const int nwg  = (gridDim.x * 256) >> 5;

    for (int m = wg; m < BN * 512 * 4; m += nwg) {            // 65536 chunks
        const int img = m >> 11;
        const int rem = m & 2047;
        const int row = rem >> 2;
        const int ch  = rem & 3;

        const int4 t4 = *reinterpret_cast<const int4*>(
            tg + ((size_t)img << 18) + row * 512 + ch * 128 + lane * 4);
        const unsigned n = (t4.x ? 1u : 0u) | (t4.y ? 2u : 0u)
                         | (t4.z ? 4u : 0u) | (t4.w ? 8u : 0u);

        // L0: 4 words per chunk (groups of 8 lanes)
        unsigned v0 = n << ((lane & 7) * 4);
        v0 |= __shfl_xor_sync(0xffffffffu, v0, 1);
        v0 |= __shfl_xor_sync(0xffffffffu, v0, 2);
        v0 |= __shfl_xor_sync(0xffffffffu, v0, 4);
        if ((lane & 7) == 0)
            g_bits[img * 8192 + row * 16 + ch * 4 + (lane >> 3)] = v0;

        if ((row & 1) == 0) {
            // L1: pixels at stride 2 -> bits 0 and 2 of each nibble
            unsigned v1 = ((n & 1u) | ((n >> 1) & 2u)) << (2 * (lane & 15));
            v1 |= __shfl_xor_sync(0xffffffffu, v1, 1);
            v1 |= __shfl_xor_sync(0xffffffffu, v1, 2);
            v1 |= __shfl_xor_sync(0xffffffffu, v1, 4);
            v1 |= __shfl_xor_sync(0xffffffffu, v1, 8);
            if ((lane & 15) == 0)
                g_bits[NW0 + img * 2048 + (row >> 1) * 8 + ch * 2 + (lane >> 4)] = v1;

            if ((row & 3) == 0) {
                // L2: pixels at stride 4 -> bit 0 of each nibble
                unsigned v2 = (n & 1u) << lane;
                v2 |= __shfl_xor_sync(0xffffffffu, v2, 1);
                v2 |= __shfl_xor_sync(0xffffffffu, v2, 2);
                v2 |= __shfl_xor_sync(0xffffffffu, v2, 4);
                v2 |= __shfl_xor_sync(0xffffffffu, v2, 8);
                v2 |= __shfl_xor_sync(0xffffffffu, v2, 16);
                if (lane == 0)
                    g_bits[NW0 + NW1 + img * 512 + (row >> 2) * 4 + ch] = v2;
            }
        }
    }
}

// ============ main fused kernel ============
struct Acc { float c, s, inter, z, ps; };

__device__ __forceinline__ void commit(Acc& a, int slot, float* s_red) {
    a.c     = warp_sum(a.c);
    a.s     = warp_sum(a.s);
    a.inter = warp_sum(a.inter);
    a.z     = warp_sum(a.z);
    a.ps    = warp_sum(a.ps);
    const int wid = threadIdx.x >> 5;
    if ((threadIdx.x & 31) == 0) {
        float* r = s_red + wid * 5;
        r[0] = a.c; r[1] = a.s; r[2] = a.inter; r[3] = a.z; r[4] = a.ps;
    }
    __syncthreads();
    if (threadIdx.x == 0) {
        float o0 = 0.f, o1 = 0.f, o2 = 0.f, o3 = 0.f, o4 = 0.f;
        #pragma unroll
        for (int w = 0; w < 8; w++) {
            o0 += s_red[w * 5 + 0]; o1 += s_red[w * 5 + 1]; o2 += s_red[w * 5 + 2];
            o3 += s_red[w * 5 + 3]; o4 += s_red[w * 5 + 4];
        }
        float* g = &g_part[slot * 5];
        g[0] = o0; g[1] = o1; g[2] = o2; g[3] = o3; g[4] = o4;
    }
}

// One 32-pixel word-task per thread. All 8 logits loads front-batched for MLP.
template<int H, int WPR, int LOG2W>
__device__ Acc do_scale(const float* __restrict__ logits,
                        const unsigned* __restrict__ bits,
                        int img, int blk) {
    const int t   = blk * 256 + threadIdx.x;     // [0, H*WPR)
    const int row = t >> LOG2W;
    const int wc  = t & (WPR - 1);

    const float* lp = logits + (size_t)img * (H * WPR * 32) + ((size_t)t << 5);
    float4 x[8];
    #pragma unroll
    for (int q = 0; q < 8; q++) x[q] = reinterpret_cast<const float4*>(lp)[q];

    const unsigned* bw = bits + img * (H * WPR) + t;
    const unsigned ctr = bw[0];
    const unsigned up  = (row > 0)      ? bw[-WPR] : 0u;
    const unsigned dn  = (row < H - 1)  ? bw[ WPR] : 0u;
    const unsigned pv  = (wc > 0)       ? bw[-1]   : 0u;
    const unsigned nx  = (wc < WPR - 1) ? bw[ 1]   : 0u;
    const unsigned Lm  = (ctr << 1) | (pv >> 31);
    const unsigned Rm  = (ctr >> 1) | (nx << 31);
    const unsigned bnd = ctr & ~(up & dn & Lm & Rm);

    Acc a;
    a.s  = (float)__popc(ctr);
    a.c  = (float)__popc(bnd);
    a.ps = 0.f; a.z = 0.f; a.inter = 0.f;

    #pragma unroll
    for (int q = 0; q < 8; q++) {
        const float p0 = fsigmoid(x[q].x), p1 = fsigmoid(x[q].y),
                    p2 = fsigmoid(x[q].z), p3 = fsigmoid(x[q].w);
        a.ps += (p0 + p1) + (p2 + p3);
        a.z  += (p0 * p0 + p1 * p1) + (p2 * p2 + p3 * p3);
        const unsigned bq = ctr >> (q * 4);
        a.inter += (bq & 1u) ? p0 : 0.f;
        a.inter += (bq & 2u) ? p1 : 0.f;
        a.inter += (bq & 4u) ? p2 : 0.f;
        a.inter += (bq & 8u) ? p3 : 0.f;
    }
    return a;
}

__global__ void __launch_bounds__(256, 4)
fused_kernel(const float* __restrict__ l0,
             const float* __restrict__ l1,
             const float* __restrict__ l2,
             const float* __restrict__ vm,
             float* __restrict__ out) {
    __shared__ float s_red[8 * 5];
    __shared__ bool  s_last;
    __shared__ float s_contrib[96];
    __shared__ float s_valid[BN];

    const int bid = blockIdx.x;
    Acc a;
    if (bid < NB2) {
        a = do_scale<128, 4, 2>(l2, g_bits + NW0 + NW1, bid / BPI2, bid % BPI2);
    } else if (bid < NB2 + NB1) {
        const int b = bid - NB2;
        a = do_scale<256, 8, 3>(l1, g_bits + NW0, b / BPI1, b % BPI1);
    } else {
        const int b = bid - NB2 - NB1;
        a = do_scale<512, 16, 4>(l0, g_bits, b / BPI0, b % BPI0);
    }
    commit(a, bid, s_red);

    __syncthreads();
    if (threadIdx.x == 0) {
        __threadfence();
        unsigned r = atomicAdd(&g_count, 1u);
        s_last = (r == NBLK - 1);
    }
    __syncthreads();
    if (!s_last) return;

    const int tid = threadIdx.x;
    if (tid == 0) g_count = 0;
    if (tid < BN) s_valid[tid] = (vm[tid] >= 0.5f) ? 1.0f : 0.0f;
    __syncthreads();

    if (tid < 96) {
        const int sc  = tid >> 5;   // 0=scale0, 1=scale1, 2=scale2
        const int img = tid & 31;
        int base, cntb;
        if      (sc == 0) { base = (NB2 + NB1) + img * BPI0; cntb = BPI0; }
        else if (sc == 1) { base = NB2 + img * BPI1;         cntb = BPI1; }
        else              { base = img * BPI2;               cntb = BPI2; }

        float C = 0.f, S = 0.f, I = 0.f, Z = 0.f, P = 0.f;
        for (int b = 0; b < cntb; b++) {
            const float* g = &g_part[(base + b) * 5];
            C += g[0]; S += g[1]; I += g[2]; Z += g[3]; P += g[4];
        }
        const float SMOOTH = 1e-5f;
        const float ws[3]     = { 1.0f / 1.75f, 0.5f / 1.75f, 0.25f / 1.75f };
        const float inv_hw[3] = { 1.0f / (512.f * 512.f), 1.0f / (256.f * 256.f), 1.0f / (128.f * 128.f) };
        float alpha = 2.0f * (1.0f - (C + SMOOTH) / (S + SMOOTH)) - 1.0f;
        alpha = fminf(alpha, 0.8f);
        const float num = Z + S - 2.0f * I + SMOOTH;
        const float den = Z + S - (1.0f + alpha) * I + SMOOTH;
        const float dou = num / den;
        const float per = (S > 0.f) ? dou : P * inv_hw[sc];
        s_contrib[tid] = ws[sc] * per * s_valid[img];
    }
    __syncthreads();
    if (tid == 0) {
        float sum = 0.f, cnt = 0.f;
        #pragma unroll
        for (int i = 0; i < 96; i++) sum += s_contrib[i];
        #pragma unroll
        for (int i = 0; i < BN; i++) cnt += s_valid[i];
        out[0] = (cnt > 0.f) ? (sum / cnt) : 0.0f;
    }
}

extern "C" void kernel_launch(void* const* d_in, const int* in_sizes, int n_in,
                              void* d_out, int out_size) {
    const float* l0 = (const float*)d_in[0];   // [8,4,512,512]
    const float* l1 = (const float*)d_in[1];   // [8,4,256,256]
    const float* l2 = (const float*)d_in[2];   // [8,4,128,128]
    const int*   tg = (const int*)d_in[3];     // [8,4,512,512]
    const float* vm = (const float*)d_in[4];   // [8,4]
    float* out = (float*)d_out;

    pack_kernel<<<1024, 256>>>(tg);
    fused_kernel<<<NBLK, 256>>>(l0, l1, l2, vm, out);
}

// round 8
// speedup vs baseline: 1.6373x; 1.2567x over previous
#include <cuda_runtime.h>
#include <cuda_bf16.h>

#define BN 32
#define BPI0 16
#define BPI1 8
#define BPI2 4
#define NB0 (BN * BPI0)        // 512
#define NB1 (BN * BPI1)        // 256
#define NB2 (BN * BPI2)        // 128
#define NBLK (NB0 + NB1 + NB2) // 896

__device__ float g_part[NBLK * 5];
__device__ unsigned g_count = 0;

__device__ __forceinline__ float warp_sum(float v) {
    #pragma unroll
    for (int o = 16; o > 0; o >>= 1) v += __shfl_down_sync(0xffffffffu, v, o);
    return v;
}

__device__ __forceinline__ float fsigmoid(float x) {
    return __fdividef(1.0f, 1.0f + __expf(-x));
}

struct Acc { float c, s, inter, z, ps; };

__device__ __forceinline__ void commit(Acc& a, int slot, float* s_red) {
    a.c     = warp_sum(a.c);
    a.s     = warp_sum(a.s);
    a.inter = warp_sum(a.inter);
    a.z     = warp_sum(a.z);
    a.ps    = warp_sum(a.ps);
    const int wid = threadIdx.x >> 5;
    if ((threadIdx.x & 31) == 0) {
        float* r = s_red + wid * 5;
        r[0] = a.c; r[1] = a.s; r[2] = a.inter; r[3] = a.z; r[4] = a.ps;
    }
    __syncthreads();
    if (threadIdx.x == 0) {
        float o0 = 0.f, o1 = 0.f, o2 = 0.f, o3 = 0.f, o4 = 0.f;
        #pragma unroll
        for (int w = 0; w < 8; w++) {
            o0 += s_red[w * 5 + 0]; o1 += s_red[w * 5 + 1]; o2 += s_red[w * 5 + 2];
            o3 += s_red[w * 5 + 3]; o4 += s_red[w * 5 + 4];
        }
        float* g = &g_part[slot * 5];
        g[0] = o0; g[1] = o1; g[2] = o2; g[3] = o3; g[4] = o4;
    }
}

// Process one row of 4 pixels held in t (center), u (up), d (down) with
// horizontal edge values lft (left of px0) and rgt (right of px3).
__device__ __forceinline__ void px_row(int4 t, int4 u, int4 d, int lft, int rgt,
                                       float4 x, Acc& a, int& ci, int& si) {
    const float p0 = fsigmoid(x.x), p1 = fsigmoid(x.y),
                p2 = fsigmoid(x.z), p3 = fsigmoid(x.w);
    a.ps += (p0 + p1) + (p2 + p3);
    a.z  += (p0 * p0 + p1 * p1) + (p2 * p2 + p3 * p3);
    if (t.x) { si++; a.inter += p0; if (!(u.x && d.x && lft && t.y)) ci++; }
    if (t.y) { si++; a.inter += p1; if (!(u.y && d.y && t.x && t.z)) ci++; }
    if (t.z) { si++; a.inter += p2; if (!(u.z && d.z && t.y && t.w)) ci++; }
    if (t.w) { si++; a.inter += p3; if (!(u.w && d.w && t.z && rgt)) ci++; }
}

// ---- scale 0: 512x512, orig stride 1. warp-iter = row-pair x 128px chunk ----
__device__ Acc do_scale0(const float* __restrict__ lg, const int* __restrict__ tg,
                         int wlocal) {   // wlocal in [0,128)
    Acc a = {0.f, 0.f, 0.f, 0.f, 0.f};
    int ci = 0, si = 0;
    const int lane = threadIdx.x & 31;
    #pragma unroll 2
    for (int i = 0; i < 8; i++) {
        const int task = i * 128 + wlocal;          // [0,1024)
        const int rp = task >> 2, ch = task & 3;
        const int r0 = rp * 2, r1 = r0 + 1;
        const int col = ch * 128 + lane * 4;
        const int* rowA = tg + r0 * 512 + col;

        const int4 tA = *(const int4*)rowA;
        const int4 tB = *(const int4*)(rowA + 512);
        const int4 tU = (r0 > 0)   ? *(const int4*)(rowA - 512)  : make_int4(0,0,0,0);
        const int4 tD = (r1 < 511) ? *(const int4*)(rowA + 1024) : make_int4(0,0,0,0);
        const float4 xA = *(const float4*)(lg + r0 * 512 + col);
        const float4 xB = *(const float4*)(lg + r1 * 512 + col);

        int lA = __shfl_up_sync(0xffffffffu, tA.w, 1);
        int lB = __shfl_up_sync(0xffffffffu, tB.w, 1);
        int rA = __shfl_down_sync(0xffffffffu, tA.x, 1);
        int rB = __shfl_down_sync(0xffffffffu, tB.x, 1);
        if (lane == 0)  { lA = (ch > 0) ? rowA[-1]       : 0;
                          lB = (ch > 0) ? rowA[512 - 1]  : 0; }
        if (lane == 31) { rA = (ch < 3) ? rowA[4]        : 0;
                          rB = (ch < 3) ? rowA[512 + 4]  : 0; }

        px_row(tA, tU, tB, lA, rA, xA, a, ci, si);
        px_row(tB, tA, tD, lB, rB, xB, a, ci, si);
    }
    a.c = (float)ci; a.s = (float)si;
    return a;
}

// ---- scale 1: 256x256, orig stride 2. warp-iter = s1 row-pair x 64 s1-px ----
__device__ Acc do_scale1(const float* __restrict__ lg, const int* __restrict__ tg,
                         int wlocal) {   // wlocal in [0,64)
    Acc a = {0.f, 0.f, 0.f, 0.f, 0.f};
    int ci = 0, si = 0;
    const int lane = threadIdx.x & 31;
    #pragma unroll 2
    for (int i = 0; i < 8; i++) {
        const int task = i * 64 + wlocal;           // [0,512)
        const int rp = task >> 2, ch = task & 3;
        const int r0 = rp * 2, r1 = r0 + 1;         // s1 rows
        const int oA = rp * 4, oB = oA + 2;         // orig rows
        const int ocol = ch * 128 + lane * 4;
        const int* rowA = tg + oA * 512 + ocol;

        const int4 tA = *(const int4*)rowA;
        const int4 tB = *(const int4*)(rowA + 1024);
        const int4 tU = (r0 > 0)   ? *(const int4*)(rowA - 1024) : make_int4(0,0,0,0);
        const int4 tD = (r1 < 255) ? *(const int4*)(rowA + 2048) : make_int4(0,0,0,0);
        const float2 xA = *(const float2*)(lg + r0 * 256 + ch * 64 + lane * 2);
        const float2 xB = *(const float2*)(lg + r1 * 256 + ch * 64 + lane * 2);

        int lA = __shfl_up_sync(0xffffffffu, tA.z, 1);
        int lB = __shfl_up_sync(0xffffffffu, tB.z, 1);
        int rA = __shfl_down_sync(0xffffffffu, tA.x, 1);
        int rB = __shfl_down_sync(0xffffffffu, tB.x, 1);
        if (lane == 0)  { lA = (ch > 0) ? rowA[-2]        : 0;
                          lB = (ch > 0) ? rowA[1024 - 2]  : 0; }
        if (lane == 31) { rA = (ch < 3) ? rowA[4]         : 0;
                          rB = (ch < 3) ? rowA[1024 + 4]  : 0; }

        // row A (s1 row r0): up=tU, dn=tB. lane px: (tA.x, tA.z)
        {
            const float p0 = fsigmoid(xA.x), p1 = fsigmoid(xA.y);
            a.ps += p0 + p1; a.z += p0 * p0 + p1 * p1;
            if (tA.x) { si++; a.inter += p0; if (!(tU.x && tB.x && lA   && tA.z)) ci++; }
            if (tA.z) { si++; a.inter += p1; if (!(tU.z && tB.z && tA.x && rA  )) ci++; }
        }
        // row B (s1 row r1): up=tA, dn=tD
        {
            const float p0 = fsigmoid(xB.x), p1 = fsigmoid(xB.y);
            a.ps += p0 + p1; a.z += p0 * p0 + p1 * p1;
            if (tB.x) { si++; a.inter += p0; if (!(tA.x && tD.x && lB   && tB.z)) ci++; }
            if (tB.z) { si++; a.inter += p1; if (!(tA.z && tD.z && tB.x && rB  )) ci++; }
        }
    }
    a.c = (float)ci; a.s = (float)si;
    return a;
}

// ---- scale 2: 128x128, orig stride 4. warp-iter = s2 row-pair x 32 s2-px ----
__device__ Acc do_scale2(const float* __restrict__ lg, const int* __restrict__ tg,
                         int wlocal) {   // wlocal in [0,32)
    Acc a = {0.f, 0.f, 0.f, 0.f, 0.f};
    int ci = 0, si = 0;
    const int lane = threadIdx.x & 31;
    #pragma unroll 2
    for (int i = 0; i < 8; i++) {
        const int task = i * 32 + wlocal;           // [0,256)
        const int rp = task >> 2, ch = task & 3;
        const int r0 = rp * 2, r1 = r0 + 1;         // s2 rows
        const int oA = rp * 8, oB = oA + 4;         // orig rows
        const int ocol = ch * 128 + lane * 4;
        const int* rowA = tg + oA * 512 + ocol;

        const int tAv = rowA[0];
        const int tBv = rowA[2048];
        const int tUv = (r0 > 0)   ? rowA[-2048] : 0;
        const int tDv = (r1 < 127) ? rowA[4096]  : 0;
        const float xA = lg[r0 * 128 + ch * 32 + lane];
        const float xB = lg[r1 * 128 + ch * 32 + lane];

        int lA = __shfl_up_sync(0xffffffffu, tAv, 1);
        int lB = __shfl_up_sync(0xffffffffu, tBv, 1);
        int rA = __shfl_down_sync(0xffffffffu, tAv, 1);
        int rB = __shfl_down_sync(0xffffffffu, tBv, 1);
        if (lane == 0)  { lA = (ch > 0) ? rowA[-4]        : 0;
                          lB = (ch > 0) ? rowA[2048 - 4]  : 0; }
        if (lane == 31) { rA = (ch < 3) ? rowA[4]         : 0;
                          rB = (ch < 3) ? rowA[2048 + 4]  : 0; }

        const float p0 = fsigmoid(xA), p1 = fsigmoid(xB);
        a.ps += p0 + p1; a.z += p0 * p0 + p1 * p1;
        if (tAv) { si++; a.inter += p0; if (!(tUv && tBv && lA && rA)) ci++; }
        if (tBv) { si++; a.inter += p1; if (!(tAv && tDv && lB && rB)) ci++; }
    }
    a.c = (float)ci; a.s = (float)si;
    return a;
}

__global__ void __launch_bounds__(256, 5)
fused_kernel(const float* __restrict__ l0,
             const float* __restrict__ l1,
             const float* __restrict__ l2,
             const int*   __restrict__ tg,
             const float* __restrict__ vm,
             float* __restrict__ out) {
    __shared__ float s_red[8 * 5];
    __shared__ bool  s_last;
    __shared__ float s_contrib[96];
    __shared__ float s_valid[BN];

    const int bid = blockIdx.x;
    const int wid = threadIdx.x >> 5;
    Acc a;
    if (bid < NB0) {                                        // scale 0 (heaviest first)
        const int img = bid >> 4;
        const int wlocal = (bid & 15) * 8 + wid;            // [0,128)
        a = do_scale0(l0 + (size_t)img * 512 * 512, tg + (size_t)img * 512 * 512, wlocal);
    } else if (bid < NB0 + NB1) {                           // scale 1
        const int b = bid - NB0;
        const int img = b >> 3;
        const int wlocal = (b & 7) * 8 + wid;               // [0,64)
        a = do_scale1(l1 + (size_t)img * 256 * 256, tg + (size_t)img * 512 * 512, wlocal);
    } else {                                                // scale 2
        const int b = bid - NB0 - NB1;
        const int img = b >> 2;
        const int wlocal = (b & 3) * 8 + wid;               // [0,32)
        a = do_scale2(l2 + (size_t)img * 128 * 128, tg + (size_t)img * 512 * 512, wlocal);
    }
    commit(a, bid, s_red);

    __syncthreads();
    if (threadIdx.x == 0) {
        __threadfence();
        unsigned r = atomicAdd(&g_count, 1u);
        s_last = (r == NBLK - 1);
    }
    __syncthreads();
    if (!s_last) return;

    const int tid = threadIdx.x;
    if (tid == 0) g_count = 0;
    if (tid < BN) s_valid[tid] = (vm[tid] >= 0.5f) ? 1.0f : 0.0f;
    __syncthreads();

    if (tid < 96) {
        const int sc  = tid >> 5;   // 0,1,2
        const int img = tid & 31;
        int base, cntb;
        if      (sc == 0) { base = img * BPI0;             cntb = BPI0; }
        else if (sc == 1) { base = NB0 + img * BPI1;       cntb = BPI1; }
        else              { base = NB0 + NB1 + img * BPI2; cntb = BPI2; }

        float C = 0.f, S = 0.f, I = 0.f, Z = 0.f, P = 0.f;
        for (int b = 0; b < cntb; b++) {
            const float* g = &g_part[(base + b) * 5];
            C += g[0]; S += g[1]; I += g[2]; Z += g[3]; P += g[4];
        }
        const float SMOOTH = 1e-5f;
        const float ws[3]     = { 1.0f / 1.75f, 0.5f / 1.75f, 0.25f / 1.75f };
        const float inv_hw[3] = { 1.0f / (512.f * 512.f), 1.0f / (256.f * 256.f), 1.0f / (128.f * 128.f) };
        float alpha = 2.0f * (1.0f - (C + SMOOTH) / (S + SMOOTH)) - 1.0f;
        alpha = fminf(alpha, 0.8f);
        const float num = Z + S - 2.0f * I + SMOOTH;
        const float den = Z + S - (1.0f + alpha) * I + SMOOTH;
        const float dou = num / den;
        const float per = (S > 0.f) ? dou : P * inv_hw[sc];
        s_contrib[tid] = ws[sc] * per * s_valid[img];
    }
    __syncthreads();
    if (tid == 0) {
        float sum = 0.f, cnt = 0.f;
        #pragma unroll
        for (int i = 0; i < 96; i++) sum += s_contrib[i];
        #pragma unroll
        for (int i = 0; i < BN; i++) cnt += s_valid[i];
        out[0] = (cnt > 0.f) ? (sum / cnt) : 0.0f;
    }
}

extern "C" void kernel_launch(void* const* d_in, const int* in_sizes, int n_in,
                              void* d_out, int out_size) {
    const float* l0 = (const float*)d_in[0];   // [8,4,512,512]
    const float* l1 = (const float*)d_in[1];   // [8,4,256,256]
    const float* l2 = (const float*)d_in[2];   // [8,4,128,128]
    const int*   tg = (const int*)d_in[3];     // [8,4,512,512]
    const float* vm = (const float*)d_in[4];   // [8,4]
    float* out = (float*)d_out;

    fused_kernel<<<NBLK, 256>>>(l0, l1, l2, tg, vm, out);
}

// round 9
// speedup vs baseline: 1.7610x; 1.0755x over previous
#include <cuda_runtime.h>
#include <cuda_bf16.h>

#define BN 32
#define BPI0 16
#define BPI1 8
#define BPI2 4
#define NB0 (BN * BPI0)        // 512
#define NB1 (BN * BPI1)        // 256
#define NB2 (BN * BPI2)        // 128
#define NBLK (NB0 + NB1 + NB2) // 896

__device__ float g_part[NBLK * 5];
__device__ unsigned g_count = 0;

__device__ __forceinline__ float warp_sum(float v) {
    #pragma unroll
    for (int o = 16; o > 0; o >>= 1) v += __shfl_down_sync(0xffffffffu, v, o);
    return v;
}

__device__ __forceinline__ float fsigmoid(float x) {
    return __fdividef(1.0f, 1.0f + __expf(-x));
}

struct Acc { float c, s, inter, z, ps; };

__device__ __forceinline__ void commit(Acc& a, int slot, float* s_red) {
    a.c     = warp_sum(a.c);
    a.s     = warp_sum(a.s);
    a.inter = warp_sum(a.inter);
    a.z     = warp_sum(a.z);
    a.ps    = warp_sum(a.ps);
    const int wid = threadIdx.x >> 5;
    if ((threadIdx.x & 31) == 0) {
        float* r = s_red + wid * 5;
        r[0] = a.c; r[1] = a.s; r[2] = a.inter; r[3] = a.z; r[4] = a.ps;
    }
    __syncthreads();
    if (threadIdx.x == 0) {
        float o0 = 0.f, o1 = 0.f, o2 = 0.f, o3 = 0.f, o4 = 0.f;
        #pragma unroll
        for (int w = 0; w < 8; w++) {
            o0 += s_red[w * 5 + 0]; o1 += s_red[w * 5 + 1]; o2 += s_red[w * 5 + 2];
            o3 += s_red[w * 5 + 3]; o4 += s_red[w * 5 + 4];
        }
        float* g = &g_part[slot * 5];
        g[0] = o0; g[1] = o1; g[2] = o2; g[3] = o3; g[4] = o4;
    }
}

// One row of 4 pixels. t/u/d hold 0/1 ints; lft/rgt are 0/1 edge values.
// Pure integer boundary math (LOP3 + IADD3), sigmoid float stream.
__device__ __forceinline__ void px_row(int4 t, int4 u, int4 d, int lft, int rgt,
                                       float4 x, Acc& a, int& ci, int& si) {
    const float p0 = fsigmoid(x.x), p1 = fsigmoid(x.y),
                p2 = fsigmoid(x.z), p3 = fsigmoid(x.w);
    a.ps += (p0 + p1) + (p2 + p3);
    a.z  += (p0 * p0 + p1 * p1) + (p2 * p2 + p3 * p3);
    si += (t.x + t.y) + (t.z + t.w);
    ci += (t.x & ~(u.x & d.x & lft & t.y))
        + (t.y & ~(u.y & d.y & t.x & t.z))
        + (t.z & ~(u.z & d.z & t.y & t.w))
        + (t.w & ~(u.w & d.w & t.z & rgt));
    a.inter += ((t.x ? p0 : 0.f) + (t.y ? p1 : 0.f))
             + ((t.z ? p2 : 0.f) + (t.w ? p3 : 0.f));
}

// ---- scale 0: 512x512. warp-iter = row-pair x 128px chunk ----
__device__ Acc do_scale0(const float* __restrict__ lg, const int* __restrict__ tg,
                         int wlocal) {   // wlocal in [0,128)
    Acc a = {0.f, 0.f, 0.f, 0.f, 0.f};
    int ci = 0, si = 0;
    const int lane = threadIdx.x & 31;
    #pragma unroll 2
    for (int i = 0; i < 8; i++) {
        const int task = i * 128 + wlocal;
        const int rp = task >> 2, ch = task & 3;
        const int r0 = rp * 2, r1 = r0 + 1;
        const int col = ch * 128 + lane * 4;
        const int* rowA = tg + r0 * 512 + col;

        const int4 tA = *(const int4*)rowA;
        const int4 tB = *(const int4*)(rowA + 512);
        const int4 tU = (r0 > 0)   ? *(const int4*)(rowA - 512)  : make_int4(0,0,0,0);
        const int4 tD = (r1 < 511) ? *(const int4*)(rowA + 1024) : make_int4(0,0,0,0);
        const float4 xA = *(const float4*)(lg + r0 * 512 + col);
        const float4 xB = *(const float4*)(lg + r1 * 512 + col);

        int lA = __shfl_up_sync(0xffffffffu, tA.w, 1);
        int lB = __shfl_up_sync(0xffffffffu, tB.w, 1);
        int rA = __shfl_down_sync(0xffffffffu, tA.x, 1);
        int rB = __shfl_down_sync(0xffffffffu, tB.x, 1);
        if (lane == 0)  { lA = (ch > 0) ? rowA[-1]       : 0;
                          lB = (ch > 0) ? rowA[512 - 1]  : 0; }
        if (lane == 31) { rA = (ch < 3) ? rowA[4]        : 0;
                          rB = (ch < 3) ? rowA[512 + 4]  : 0; }

        px_row(tA, tU, tB, lA, rA, xA, a, ci, si);
        px_row(tB, tA, tD, lB, rB, xB, a, ci, si);
    }
    a.c = (float)ci; a.s = (float)si;
    return a;
}

// ---- scale 1: 256x256, orig stride 2 ----
__device__ Acc do_scale1(const float* __restrict__ lg, const int* __restrict__ tg,
                         int wlocal) {   // wlocal in [0,64)
    Acc a = {0.f, 0.f, 0.f, 0.f, 0.f};
    int ci = 0, si = 0;
    const int lane = threadIdx.x & 31;
    #pragma unroll 2
    for (int i = 0; i < 8; i++) {
        const int task = i * 64 + wlocal;
        const int rp = task >> 2, ch = task & 3;
        const int r0 = rp * 2, r1 = r0 + 1;         // s1 rows
        const int oA = rp * 4;                      // orig row of r0
        const int ocol = ch * 128 + lane * 4;
        const int* rowA = tg + oA * 512 + ocol;

        const int4 tA = *(const int4*)rowA;
        const int4 tB = *(const int4*)(rowA + 1024);
        const int4 tU = (r0 > 0)   ? *(const int4*)(rowA - 1024) : make_int4(0,0,0,0);
        const int4 tD = (r1 < 255) ? *(const int4*)(rowA + 2048) : make_int4(0,0,0,0);
        const float2 xA = *(const float2*)(lg + r0 * 256 + ch * 64 + lane * 2);
        const float2 xB = *(const float2*)(lg + r1 * 256 + ch * 64 + lane * 2);

        int lA = __shfl_up_sync(0xffffffffu, tA.z, 1);
        int lB = __shfl_up_sync(0xffffffffu, tB.z, 1);
        int rA = __shfl_down_sync(0xffffffffu, tA.x, 1);
        int rB = __shfl_down_sync(0xffffffffu, tB.x, 1);
        if (lane == 0)  { lA = (ch > 0) ? rowA[-2]        : 0;
                          lB = (ch > 0) ? rowA[1024 - 2]  : 0; }
        if (lane == 31) { rA = (ch < 3) ? rowA[4]         : 0;
                          rB = (ch < 3) ? rowA[1024 + 4]  : 0; }

        {
            const float p0 = fsigmoid(xA.x), p1 = fsigmoid(xA.y);
            a.ps += p0 + p1; a.z += p0 * p0 + p1 * p1;
            si += tA.x + tA.z;
            ci += (tA.x & ~(tU.x & tB.x & lA   & tA.z))
                + (tA.z & ~(tU.z & tB.z & tA.x & rA  ));
            a.inter += (tA.x ? p0 : 0.f) + (tA.z ? p1 : 0.f);
        }
        {
            const float p0 = fsigmoid(xB.x), p1 = fsigmoid(xB.y);
            a.ps += p0 + p1; a.z += p0 * p0 + p1 * p1;
            si += tB.x + tB.z;
            ci += (tB.x & ~(tA.x & tD.x & lB   & tB.z))
                + (tB.z & ~(tA.z & tD.z & tB.x & rB  ));
            a.inter += (tB.x ? p0 : 0.f) + (tB.z ? p1 : 0.f);
        }
    }
    a.c = (float)ci; a.s = (float)si;
    return a;
}

// ---- scale 2: 128x128, orig stride 4 ----
__device__ Acc do_scale2(const float* __restrict__ lg, const int* __restrict__ tg,
                         int wlocal) {   // wlocal in [0,32)
    Acc a = {0.f, 0.f, 0.f, 0.f, 0.f};
    int ci = 0, si = 0;
    const int lane = threadIdx.x & 31;
    #pragma unroll 2
    for (int i = 0; i < 8; i++) {
        const int task = i * 32 + wlocal;
        const int rp = task >> 2, ch = task & 3;
        const int r0 = rp * 2, r1 = r0 + 1;         // s2 rows
        const int oA = rp * 8;
        const int ocol = ch * 128 + lane * 4;
        const int* rowA = tg + oA * 512 + ocol;

        const int tAv = rowA[0];
        const int tBv = rowA[2048];
        const int tUv = (r0 > 0)   ? rowA[-2048] : 0;
        const int tDv = (r1 < 127) ? rowA[4096]  : 0;
        const float xA = lg[r0 * 128 + ch * 32 + lane];
        const float xB = lg[r1 * 128 + ch * 32 + lane];

        int lA = __shfl_up_sync(0xffffffffu, tAv, 1);
        int lB = __shfl_up_sync(0xffffffffu, tBv, 1);
        int rA = __shfl_down_sync(0xffffffffu, tAv, 1);
        int rB = __shfl_down_sync(0xffffffffu, tBv, 1);
        if (lane == 0)  { lA = (ch > 0) ? rowA[-4]        : 0;
                          lB = (ch > 0) ? rowA[2048 - 4]  : 0; }
        if (lane == 31) { rA = (ch < 3) ? rowA[4]         : 0;
                          rB = (ch < 3) ? rowA[2048 + 4]  : 0; }

        const float p0 = fsigmoid(xA), p1 = fsigmoid(xB);
        a.ps += p0 + p1; a.z += p0 * p0 + p1 * p1;
        si += tAv + tBv;
        ci += (tAv & ~(tUv & tBv & lA & rA))
            + (tBv & ~(tAv & tDv & lB & rB));
        a.inter += (tAv ? p0 : 0.f) + (tBv ? p1 : 0.f);
    }
    a.c = (float)ci; a.s = (float)si;
    return a;
}

__global__ void __launch_bounds__(256, 6)
fused_kernel(const float* __restrict__ l0,
             const float* __restrict__ l1,
             const float* __restrict__ l2,
             const int*   __restrict__ tg,
             const float* __restrict__ vm,
             float* __restrict__ out) {
    __shared__ float s_red[8 * 5];
    __shared__ bool  s_last;
    __shared__ float s_contrib[96];
    __shared__ float s_valid[BN];

    const int bid = blockIdx.x;
    const int wid = threadIdx.x >> 5;
    Acc a;
    if (bid < NB0) {
        const int img = bid >> 4;
        const int wlocal = (bid & 15) * 8 + wid;
        a = do_scale0(l0 + (size_t)img * 512 * 512, tg + (size_t)img * 512 * 512, wlocal);
    } else if (bid < NB0 + NB1) {
        const int b = bid - NB0;
        const int img = b >> 3;
        const int wlocal = (b & 7) * 8 + wid;
        a = do_scale1(l1 + (size_t)img * 256 * 256, tg + (size_t)img * 512 * 512, wlocal);
    } else {
        const int b = bid - NB0 - NB1;
        const int img = b >> 2;
        const int wlocal = (b & 3) * 8 + wid;
        a = do_scale2(l2 + (size_t)img * 128 * 128, tg + (size_t)img * 512 * 512, wlocal);
    }
    commit(a, bid, s_red);

    __syncthreads();
    if (threadIdx.x == 0) {
        __threadfence();
        unsigned r = atomicAdd(&g_count, 1u);
        s_last = (r == NBLK - 1);
    }
    __syncthreads();
    if (!s_last) return;

    const int tid = threadIdx.x;
    if (tid == 0) g_count = 0;
    if (tid < BN) s_valid[tid] = (vm[tid] >= 0.5f) ? 1.0f : 0.0f;
    __syncthreads();

    if (tid < 96) {
        const int sc  = tid >> 5;
        const int img = tid & 31;
        int base, cntb;
        if      (sc == 0) { base = img * BPI0;             cntb = BPI0; }
        else if (sc == 1) { base = NB0 + img * BPI1;       cntb = BPI1; }
        else              { base = NB0 + NB1 + img * BPI2; cntb = BPI2; }

        float C = 0.f, S = 0.f, I = 0.f, Z = 0.f, P = 0.f;
        for (int b = 0; b < cntb; b++) {
            const float* g = &g_part[(base + b) * 5];
            C += g[0]; S += g[1]; I += g[2]; Z += g[3]; P += g[4];
        }
        const float SMOOTH = 1e-5f;
        const float ws[3]     = { 1.0f / 1.75f, 0.5f / 1.75f, 0.25f / 1.75f };
        const float inv_hw[3] = { 1.0f / (512.f * 512.f), 1.0f / (256.f * 256.f), 1.0f / (128.f * 128.f) };
        float alpha = 2.0f * (1.0f - (C + SMOOTH) / (S + SMOOTH)) - 1.0f;
        alpha = fminf(alpha, 0.8f);
        const float num = Z + S - 2.0f * I + SMOOTH;
        const float den = Z + S - (1.0f + alpha) * I + SMOOTH;
        const float dou = num / den;
        const float per = (S > 0.f) ? dou : P * inv_hw[sc];
        s_contrib[tid] = ws[sc] * per * s_valid[img];
    }
    __syncthreads();
    if (tid == 0) {
        float sum = 0.f, cnt = 0.f;
        #pragma unroll
        for (int i = 0; i < 96; i++) sum += s_contrib[i];
        #pragma unroll
        for (int i = 0; i < BN; i++) cnt += s_valid[i];
        out[0] = (cnt > 0.f) ? (sum / cnt) : 0.0f;
    }
}

extern "C" void kernel_launch(void* const* d_in, const int* in_sizes, int n_in,
                              void* d_out, int out_size) {
    const float* l0 = (const float*)d_in[0];   // [8,4,512,512]
    const float* l1 = (const float*)d_in[1];   // [8,4,256,256]
    const float* l2 = (const float*)d_in[2];   // [8,4,128,128]
    const int*   tg = (const int*)d_in[3];     // [8,4,512,512]
    const float* vm = (const float*)d_in[4];   // [8,4]
    float* out = (float*)d_out;

    fused_kernel<<<NBLK, 256>>>(l0, l1, l2, tg, vm, out);
}

// round 10
// speedup vs baseline: 1.7830x; 1.0125x over previous
#include <cuda_runtime.h>
#include <cuda_bf16.h>

#define BN 32
#define BPI0 16
#define BPI1 8
#define BPI2 4
#define NB0 (BN * BPI0)        // 512
#define NB1 (BN * BPI1)        // 256
#define NB2 (BN * BPI2)        // 128
#define NBLK (NB0 + NB1 + NB2) // 896

__device__ float g_part[NBLK * 5];
__device__ unsigned g_count = 0;

typedef unsigned long long u64;

__device__ __forceinline__ u64 pk(float lo, float hi) {
    u64 r; asm("mov.b64 %0, {%1, %2};" : "=l"(r) : "f"(lo), "f"(hi)); return r;
}
__device__ __forceinline__ void upk(float& lo, float& hi, u64 v) {
    asm("mov.b64 {%0, %1}, %2;" : "=f"(lo), "=f"(hi) : "l"(v));
}
__device__ __forceinline__ u64 mul2(u64 a, u64 b) {
    u64 r; asm("mul.rn.f32x2 %0, %1, %2;" : "=l"(r) : "l"(a), "l"(b)); return r;
}
__device__ __forceinline__ u64 add2(u64 a, u64 b) {
    u64 r; asm("add.rn.f32x2 %0, %1, %2;" : "=l"(r) : "l"(a), "l"(b)); return r;
}
__device__ __forceinline__ u64 fma2(u64 a, u64 b, u64 c) {
    u64 r; asm("fma.rn.f32x2 %0, %1, %2, %3;" : "=l"(r) : "l"(a), "l"(b), "l"(c)); return r;
}
__device__ __forceinline__ float ex2f(float x) {
    float r; asm("ex2.approx.f32 %0, %1;" : "=f"(r) : "f"(x)); return r;
}
__device__ __forceinline__ float rcpf(float x) {
    float r; asm("rcp.approx.f32 %0, %1;" : "=f"(r) : "f"(x)); return r;
}

#define NL2E_LO (-1.4426950408889634f)

// Packed sigmoid for a pair of logits: returns (sig(x0), sig(x1)).
__device__ __forceinline__ u64 sig2(float x0, float x1, u64 nl2e, u64 one2) {
    u64 t = mul2(pk(x0, x1), nl2e);
    float t0, t1; upk(t0, t1, t);
    u64 d = add2(pk(ex2f(t0), ex2f(t1)), one2);
    float d0, d1; upk(d0, d1, d);
    return pk(rcpf(d0), rcpf(d1));
}

__device__ __forceinline__ float warp_sum(float v) {
    #pragma unroll
    for (int o = 16; o > 0; o >>= 1) v += __shfl_down_sync(0xffffffffu, v, o);
    return v;
}

struct Acc { float c, s, inter, z, ps; };

__device__ __forceinline__ void commit(Acc& a, int slot, float* s_red) {
    a.c     = warp_sum(a.c);
    a.s     = warp_sum(a.s);
    a.inter = warp_sum(a.inter);
    a.z     = warp_sum(a.z);
    a.ps    = warp_sum(a.ps);
    const int wid = threadIdx.x >> 5;
    if ((threadIdx.x & 31) == 0) {
        float* r = s_red + wid * 5;
        r[0] = a.c; r[1] = a.s; r[2] = a.inter; r[3] = a.z; r[4] = a.ps;
    }
    __syncthreads();
    if (threadIdx.x == 0) {
        float o0 = 0.f, o1 = 0.f, o2 = 0.f, o3 = 0.f, o4 = 0.f;
        #pragma unroll
        for (int w = 0; w < 8; w++) {
            o0 += s_red[w * 5 + 0]; o1 += s_red[w * 5 + 1]; o2 += s_red[w * 5 + 2];
            o3 += s_red[w * 5 + 3]; o4 += s_red[w * 5 + 4];
        }
        float* g = &g_part[slot * 5];
        g[0] = o0; g[1] = o1; g[2] = o2; g[3] = o3; g[4] = o4;
    }
}

struct PAcc { u64 ps2, z2, i2; int ci, si; };

// One row of 4 pixels, packed float math.
__device__ __forceinline__ void px_row(int4 t, int4 u, int4 d, int lft, int rgt,
                                       float4 x, PAcc& a, u64 nl2e, u64 one2) {
    const u64 p01 = sig2(x.x, x.y, nl2e, one2);
    const u64 p23 = sig2(x.z, x.w, nl2e, one2);
    a.ps2 = add2(a.ps2, p01);
    a.ps2 = add2(a.ps2, p23);
    a.z2  = fma2(p01, p01, a.z2);
    a.z2  = fma2(p23, p23, a.z2);
    float p0, p1, p2, p3;
    upk(p0, p1, p01); upk(p2, p3, p23);
    a.i2 = add2(a.i2, pk(t.x ? p0 : 0.f, t.y ? p1 : 0.f));
    a.i2 = add2(a.i2, pk(t.z ? p2 : 0.f, t.w ? p3 : 0.f));
    a.si += (t.x + t.y) + (t.z + t.w);
    a.ci += (t.x & ~(u.x & d.x & lft & t.y))
          + (t.y & ~(u.y & d.y & t.x & t.z))
          + (t.z & ~(u.z & d.z & t.y & t.w))
          + (t.w & ~(u.w & d.w & t.z & rgt));
}

__device__ __forceinline__ Acc finish(PAcc& a) {
    Acc o;
    float l, h;
    upk(l, h, a.ps2); o.ps = l + h;
    upk(l, h, a.z2);  o.z  = l + h;
    upk(l, h, a.i2);  o.inter = l + h;
    o.c = (float)a.ci; o.s = (float)a.si;
    return o;
}

// ---- scale 0: 512x512. warp-iter = row-pair x 128px chunk ----
__device__ Acc do_scale0(const float* __restrict__ lg, const int* __restrict__ tg,
                         int wlocal) {
    PAcc a; a.ps2 = 0; a.z2 = 0; a.i2 = 0; a.ci = 0; a.si = 0;
    const u64 nl2e = pk(NL2E_LO, NL2E_LO);
    const u64 one2 = pk(1.0f, 1.0f);
    const int lane = threadIdx.x & 31;
    #pragma unroll 2
    for (int i = 0; i < 8; i++) {
        const int task = i * 128 + wlocal;
        const int rp = task >> 2, ch = task & 3;
        const int r0 = rp * 2, r1 = r0 + 1;
        const int col = ch * 128 + lane * 4;
        const int* rowA = tg + r0 * 512 + col;

        const int4 tA = *(const int4*)rowA;
        const int4 tB = *(const int4*)(rowA + 512);
        const int4 tU = (r0 > 0)   ? *(const int4*)(rowA - 512)  : make_int4(0,0,0,0);
        const int4 tD = (r1 < 511) ? *(const int4*)(rowA + 1024) : make_int4(0,0,0,0);
        const float4 xA = *(const float4*)(lg + r0 * 512 + col);
        const float4 xB = *(const float4*)(lg + r1 * 512 + col);

        int lA = __shfl_up_sync(0xffffffffu, tA.w, 1);
        int lB = __shfl_up_sync(0xffffffffu, tB.w, 1);
        int rA = __shfl_down_sync(0xffffffffu, tA.x, 1);
        int rB = __shfl_down_sync(0xffffffffu, tB.x, 1);
        if (lane == 0)  { lA = (ch > 0) ? rowA[-1]       : 0;
                          lB = (ch > 0) ? rowA[512 - 1]  : 0; }
        if (lane == 31) { rA = (ch < 3) ? rowA[4]        : 0;
                          rB = (ch < 3) ? rowA[512 + 4]  : 0; }

        px_row(tA, tU, tB, lA, rA, xA, a, nl2e, one2);
        px_row(tB, tA, tD, lB, rB, xB, a, nl2e, one2);
    }
    return finish(a);
}

// ---- scale 1: 256x256, orig stride 2 ----
__device__ Acc do_scale1(const float* __restrict__ lg, const int* __restrict__ tg,
                         int wlocal) {
    PAcc a; a.ps2 = 0; a.z2 = 0; a.i2 = 0; a.ci = 0; a.si = 0;
    const u64 nl2e = pk(NL2E_LO, NL2E_LO);
    const u64 one2 = pk(1.0f, 1.0f);
    const int lane = threadIdx.x & 31;
    #pragma unroll 2
    for (int i = 0; i < 8; i++) {
        const int task = i * 64 + wlocal;
        const int rp = task >> 2, ch = task & 3;
        const int r0 = rp * 2, r1 = r0 + 1;
        const int oA = rp * 4;
        const int ocol = ch * 128 + lane * 4;
        const int* rowA = tg + oA * 512 + ocol;

        const int4 tA = *(const int4*)rowA;
        const int4 tB = *(const int4*)(rowA + 1024);
        const int4 tU = (r0 > 0)   ? *(const int4*)(rowA - 1024) : make_int4(0,0,0,0);
        const int4 tD = (r1 < 255) ? *(const int4*)(rowA + 2048) : make_int4(0,0,0,0);
        const float2 xA = *(const float2*)(lg + r0 * 256 + ch * 64 + lane * 2);
        const float2 xB = *(const float2*)(lg + r1 * 256 + ch * 64 + lane * 2);

        int lA = __shfl_up_sync(0xffffffffu, tA.z, 1);
        int lB = __shfl_up_sync(0xffffffffu, tB.z, 1);
        int rA = __shfl_down_sync(0xffffffffu, tA.x, 1);
        int rB = __shfl_down_sync(0xffffffffu, tB.x, 1);
        if (lane == 0)  { lA = (ch > 0) ? rowA[-2]        : 0;
                          lB = (ch > 0) ? rowA[1024 - 2]  : 0; }
        if (lane == 31) { rA = (ch < 3) ? rowA[4]         : 0;
                          rB = (ch < 3) ? rowA[1024 + 4]  : 0; }

        const u64 pA = sig2(xA.x, xA.y, nl2e, one2);
        const u64 pB = sig2(xB.x, xB.y, nl2e, one2);
        a.ps2 = add2(a.ps2, pA);
        a.ps2 = add2(a.ps2, pB);
        a.z2  = fma2(pA, pA, a.z2);
        a.z2  = fma2(pB, pB, a.z2);
        float pA0, pA1, pB0, pB1;
        upk(pA0, pA1, pA); upk(pB0, pB1, pB);
        a.i2 = add2(a.i2, pk(tA.x ? pA0 : 0.f, tA.z ? pA1 : 0.f));
        a.i2 = add2(a.i2, pk(tB.x ? pB0 : 0.f, tB.z ? pB1 : 0.f));
        a.si += (tA.x + tA.z) + (tB.x + tB.z);
        a.ci += (tA.x & ~(tU.x & tB.x & lA   & tA.z))
              + (tA.z & ~(tU.z & tB.z & tA.x & rA  ))
              + (tB.x & ~(tA.x & tD.x & lB   & tB.z))
              + (tB.z & ~(tA.z & tD.z & tB.x & rB  ));
    }
    return finish(a);
}

// ---- scale 2: 128x128, orig stride 4 ----
__device__ Acc do_scale2(const float* __restrict__ lg, const int* __restrict__ tg,
                         int wlocal) {
    PAcc a; a.ps2 = 0; a.z2 = 0; a.i2 = 0; a.ci = 0; a.si = 0;
    const u64 nl2e = pk(NL2E_LO, NL2E_LO);
    const u64 one2 = pk(1.0f, 1.0f);
    const int lane = threadIdx.x & 31;
    #pragma unroll 2
    for (int i = 0; i < 8; i++) {
        const int task = i * 32 + wlocal;
        const int rp = task >> 2, ch = task & 3;
        const int r0 = rp * 2, r1 = r0 + 1;
        const int oA = rp * 8;
        const int ocol = ch * 128 + lane * 4;
        const int* rowA = tg + oA * 512 + ocol;

        const int tAv = rowA[0];
        const int tBv = rowA[2048];
        const int tUv = (r0 > 0)   ? rowA[-2048] : 0;
        const int tDv = (r1 < 127) ? rowA[4096]  : 0;
        const float xA = lg[r0 * 128 + ch * 32 + lane];
        const float xB = lg[r1 * 128 + ch * 32 + lane];

        int lA = __shfl_up_sync(0xffffffffu, tAv, 1);
        int lB = __shfl_up_sync(0xffffffffu, tBv, 1);
        int rA = __shfl_down_sync(0xffffffffu, tAv, 1);
        int rB = __shfl_down_sync(0xffffffffu, tBv, 1);
        if (lane == 0)  { lA = (ch > 0) ? rowA[-4]        : 0;
                          lB = (ch > 0) ? rowA[2048 - 4]  : 0; }
        if (lane == 31) { rA = (ch < 3) ? rowA[4]         : 0;
                          rB = (ch < 3) ? rowA[2048 + 4]  : 0; }

        const u64 p = sig2(xA, xB, nl2e, one2);
        a.ps2 = add2(a.ps2, p);
        a.z2  = fma2(p, p, a.z2);
        float p0, p1; upk(p0, p1, p);
        a.i2 = add2(a.i2, pk(tAv ? p0 : 0.f, tBv ? p1 : 0.f));
        a.si += tAv + tBv;
        a.ci += (tAv & ~(tUv & tBv & lA & rA))
              + (tBv & ~(tAv & tDv & lB & rB));
    }
    return finish(a);
}

__global__ void __launch_bounds__(256, 5)
fused_kernel(const float* __restrict__ l0,
             const float* __restrict__ l1,
             const float* __restrict__ l2,
             const int*   __restrict__ tg,
             const float* __restrict__ vm,
             float* __restrict__ out) {
    __shared__ float s_red[8 * 5];
    __shared__ bool  s_last;
    __shared__ float s_contrib[96];
    __shared__ float s_valid[BN];

    const int bid = blockIdx.x;
    const int wid = threadIdx.x >> 5;
    Acc a;
    if (bid < NB0) {
        const int img = bid >> 4;
        const int wlocal = (bid & 15) * 8 + wid;
        a = do_scale0(l0 + (size_t)img * 512 * 512, tg + (size_t)img * 512 * 512, wlocal);
    } else if (bid < NB0 + NB1) {
        const int b = bid - NB0;
        const int img = b >> 3;
        const int wlocal = (b & 7) * 8 + wid;
        a = do_scale1(l1 + (size_t)img * 256 * 256, tg + (size_t)img * 512 * 512, wlocal);
    } else {
        const int b = bid - NB0 - NB1;
        const int img = b >> 2;
        const int wlocal = (b & 3) * 8 + wid;
        a = do_scale2(l2 + (size_t)img * 128 * 128, tg + (size_t)img * 512 * 512, wlocal);
    }
    commit(a, bid, s_red);

    __syncthreads();
    if (threadIdx.x == 0) {
        __threadfence();
        unsigned r = atomicAdd(&g_count, 1u);
        s_last = (r == NBLK - 1);
    }
    __syncthreads();
    if (!s_last) return;

    const int tid = threadIdx.x;
    if (tid == 0) g_count = 0;
    if (tid < BN) s_valid[tid] = (vm[tid] >= 0.5f) ? 1.0f : 0.0f;
    __syncthreads();

    if (tid < 96) {
        const int sc  = tid >> 5;
        const int img = tid & 31;
        int base, cntb;
        if      (sc == 0) { base = img * BPI0;             cntb = BPI0; }
        else if (sc == 1) { base = NB0 + img * BPI1;       cntb = BPI1; }
        else              { base = NB0 + NB1 + img * BPI2; cntb = BPI2; }

        float C = 0.f, S = 0.f, I = 0.f, Z = 0.f, P = 0.f;
        for (int b = 0; b < cntb; b++) {
            const float* g = &g_part[(base + b) * 5];
            C += g[0]; S += g[1]; I += g[2]; Z += g[3]; P += g[4];
        }
        const float SMOOTH = 1e-5f;
        const float ws[3]     = { 1.0f / 1.75f, 0.5f / 1.75f, 0.25f / 1.75f };
        const float inv_hw[3] = { 1.0f / (512.f * 512.f), 1.0f / (256.f * 256.f), 1.0f / (128.f * 128.f) };
        float alpha = 2.0f * (1.0f - (C + SMOOTH) / (S + SMOOTH)) - 1.0f;
        alpha = fminf(alpha, 0.8f);
        const float num = Z + S - 2.0f * I + SMOOTH;
        const float den = Z + S - (1.0f + alpha) * I + SMOOTH;
        const float dou = num / den;
        const float per = (S > 0.f) ? dou : P * inv_hw[sc];
        s_contrib[tid] = ws[sc] * per * s_valid[img];
    }
    __syncthreads();
    if (tid == 0) {
        float sum = 0.f, cnt = 0.f;
        #pragma unroll
        for (int i = 0; i < 96; i++) sum += s_contrib[i];
        #pragma unroll
        for (int i = 0; i < BN; i++) cnt += s_valid[i];
        out[0] = (cnt > 0.f) ? (sum / cnt) : 0.0f;
    }
}

extern "C" void kernel_launch(void* const* d_in, const int* in_sizes, int n_in,
                              void* d_out, int out_size) {
    const float* l0 = (const float*)d_in[0];   // [8,4,512,512]
    const float* l1 = (const float*)d_in[1];   // [8,4,256,256]
    const float* l2 = (const float*)d_in[2];   // [8,4,128,128]
    const int*   tg = (const int*)d_in[3];     // [8,4,512,512]
    const float* vm = (const float*)d_in[4];   // [8,4]
    float* out = (float*)d_out;

    fused_kernel<<<NBLK, 256>>>(l0, l1, l2, tg, vm, out);
}